// round 7
// baseline (speedup 1.0000x reference)
#include <cuda_runtime.h>

#define BB 4096
#define TT 4096
#define GAMMA  0.99f
#define CLIPV  5.0f

#define THREADS 512
#define LPT 8                   // columns per thread (512*8 = 4096)
#define NW (THREADS / 32)       // 16 warps
#define NBLK 444                // 3 blocks/SM * 148 SMs — all co-resident
#define CROWS 4                 // phase-A rows cached in smem per block
#define POOL0 (CROWS * NBLK)    // 1776: first pool row for phase-C stealing

#define GAMMA8   0.92274469f    // 0.99^8
#define GAMMA256 0.07631496f    // 0.99^256
#define LOG2G   (-0.014499569695115089f)   // log2(0.99)

__device__ float g_partial[NBLK * TT];
__device__ float g_colmean[TT];
__device__ unsigned g_cnt[2];
__device__ volatile unsigned g_epoch;
__device__ unsigned g_rowcnt;

__device__ __forceinline__ void grid_barrier(unsigned* cnt, unsigned target) {
    __syncthreads();
    if (threadIdx.x == 0) {
        __threadfence();
        if (atomicAdd(cnt, 1u) == NBLK - 1u) {
            *cnt = 0;
            __threadfence();
            g_epoch = target;
        } else {
            while (g_epoch != target) __nanosleep(64);
            __threadfence();
        }
    }
    __syncthreads();
}

// -----------------------------------------------------------------------------
__global__ __launch_bounds__(THREADS, 3)
void fused_all(const float* __restrict__ log_probs,
               const float* __restrict__ logits,
               const float* __restrict__ weight,
               const float* __restrict__ baselines,
               float* __restrict__ out) {
    extern __shared__ float sc[];          // [CROWS * 4096] cached (cum - baselines)

    __shared__ float s_w[2][NW];
    __shared__ float s_s[2][NW];
    __shared__ float s_pb[NW * 32];
    __shared__ float s_r[NW];
    __shared__ unsigned s_base;
    __shared__ int s_row;

    const int tid  = threadIdx.x;
    const int lane = tid & 31;
    const int wrp  = tid >> 5;
    const int bid  = blockIdx.x;

    if (tid == 0) s_base = g_epoch;
    __syncthreads();
    const unsigned base_e = s_base;

    float* gen = out;
    float* cum = out + BB;

    const float pw = exp2f((float)(31 - lane) * 8.0f * LOG2G);
    const long coff = (long)tid * LPT;

    float pacc[LPT];
#pragma unroll
    for (int k = 0; k < LPT; k++) pacc[k] = 0.0f;

    // ============================ PHASE A ====================================
    int buf = 0;
    int kiter = 0;
    for (int b = bid; b < BB; b += NBLK, kiter++) {
        const long base = (long)b * TT + coff;
        const float4* lgp = reinterpret_cast<const float4*>(logits + base);
        const float4* wtp = reinterpret_cast<const float4*>(weight + base);

        float c[LPT];
#pragma unroll
        for (int i = 0; i < LPT / 4; i++) {
            float4 lg = __ldcs(lgp + i);
            float4 wt = __ldcs(wtp + i);
            float xs[4] = {lg.x, lg.y, lg.z, lg.w};
            float ws[4] = {wt.x, wt.y, wt.z, wt.w};
#pragma unroll
            for (int k = 0; k < 4; k++) {
                float x  = xs[k];
                float ls = fminf(x, 0.0f) - __logf(1.0f + __expf(-fabsf(x)));
                c[i * 4 + k] = ws[k] * ls;
            }
        }

        float carry = 0.0f;
#pragma unroll
        for (int i = LPT - 1; i >= 0; i--) {
            carry = c[i] + GAMMA * carry;
            c[i] = carry;
        }

        float v = carry;
        float f = GAMMA8;
#pragma unroll
        for (int step = 1; step < 32; step <<= 1) {
            float up = __shfl_down_sync(0xFFFFFFFFu, v, step);
            if (lane + step < 32) v += f * up;
            f *= f;
        }
        if (lane == 0) s_w[buf][wrp] = v;
        __syncthreads();

        if (wrp == 0 && lane < NW) {
            float x = s_w[buf][lane];
            float g = GAMMA256;
#pragma unroll
            for (int step = 1; step < NW; step <<= 1) {
                float up = __shfl_down_sync(0xFFFFu, x, step, NW);
                if (lane + step < NW) x += g * up;
                g *= g;
            }
            s_s[buf][lane] = x;
        }
        __syncthreads();

        float ve = __shfl_down_sync(0xFFFFFFFFu, v, 1);
        if (lane == 31) ve = 0.0f;
        float Xw = (wrp + 1 < NW) ? s_s[buf][wrp + 1] : 0.0f;
        float T  = ve + pw * Xw;

        float p = GAMMA;
#pragma unroll
        for (int k = LPT - 1; k >= 0; k--) {
            c[k] = fmaf(p, T, c[k]);
            p *= GAMMA;
        }

        float4* cp = reinterpret_cast<float4*>(cum + base);
        const float4* bp = reinterpret_cast<const float4*>(baselines + base);
        float d[LPT];
#pragma unroll
        for (int i = 0; i < LPT / 4; i++) {
            cp[i] = make_float4(c[i * 4 + 0], c[i * 4 + 1], c[i * 4 + 2], c[i * 4 + 3]);
            float4 ba = bp[i];
            d[i * 4 + 0] = c[i * 4 + 0] - ba.x;
            d[i * 4 + 1] = c[i * 4 + 1] - ba.y;
            d[i * 4 + 2] = c[i * 4 + 2] - ba.z;
            d[i * 4 + 3] = c[i * 4 + 3] - ba.w;
            pacc[i * 4 + 0] += d[i * 4 + 0];
            pacc[i * 4 + 1] += d[i * 4 + 1];
            pacc[i * 4 + 2] += d[i * 4 + 2];
            pacc[i * 4 + 3] += d[i * 4 + 3];
        }
        // cache (cum - baselines) for the block's first CROWS rows (L2-cold by phase C)
        if (kiter < CROWS) {
            float4* scp = reinterpret_cast<float4*>(sc + kiter * TT) + tid * (LPT / 4);
#pragma unroll
            for (int i = 0; i < LPT / 4; i++)
                scp[i] = make_float4(d[i*4+0], d[i*4+1], d[i*4+2], d[i*4+3]);
        }
        buf ^= 1;
    }

    {
        float4* pp = reinterpret_cast<float4*>(g_partial + (long)bid * TT + coff);
#pragma unroll
        for (int i = 0; i < LPT / 4; i++)
            pp[i] = make_float4(pacc[i*4+0], pacc[i*4+1], pacc[i*4+2], pacc[i*4+3]);
    }

    grid_barrier(&g_cnt[0], base_e + 1);

    // ============================ PHASE B ====================================
    if (bid < 128) {
        const int c0 = bid * 32;
        float a = 0.0f;
        for (int r = wrp; r < NBLK; r += NW)
            a += g_partial[(long)r * TT + c0 + lane];
        s_pb[wrp * 32 + lane] = a;
        __syncthreads();
        if (wrp == 0) {
            float m = 0.0f;
#pragma unroll
            for (int k = 0; k < NW; k++) m += s_pb[k * 32 + lane];
            g_colmean[c0 + lane] = m * (1.0f / BB);
        }
    } else if (bid == 128 && tid == 0) {
        g_rowcnt = 0;
    }

    grid_barrier(&g_cnt[1], base_e + 2);

    // ============================ PHASE C ====================================
    const float4* mp = reinterpret_cast<const float4*>(g_colmean + coff);
    const float4 m0 = mp[0], m1 = mp[1];
    const float mm[LPT] = {m0.x, m0.y, m0.z, m0.w, m1.x, m1.y, m1.z, m1.w};

    // C1: the block's CROWS smem-cached rows — only log_probs touches memory
    for (int k = 0; k < CROWS; k++) {
        const int b = bid + k * NBLK;
        const float4* lp = reinterpret_cast<const float4*>(log_probs + (long)b * TT + coff);
        const float4* scp = reinterpret_cast<const float4*>(sc + k * TT) + tid * (LPT / 4);

        float acc = 0.0f;
#pragma unroll
        for (int i = 0; i < LPT / 4; i++) {
            float4 dv = scp[i];
            float4 lv = __ldcs(lp + i);
            float a;
            a = fminf(fmaxf(dv.x - mm[i*4+0], -CLIPV), CLIPV); acc = fmaf(a, lv.x, acc);
            a = fminf(fmaxf(dv.y - mm[i*4+1], -CLIPV), CLIPV); acc = fmaf(a, lv.y, acc);
            a = fminf(fmaxf(dv.z - mm[i*4+2], -CLIPV), CLIPV); acc = fmaf(a, lv.z, acc);
            a = fminf(fmaxf(dv.w - mm[i*4+3], -CLIPV), CLIPV); acc = fmaf(a, lv.w, acc);
        }
#pragma unroll
        for (int off = 16; off > 0; off >>= 1)
            acc += __shfl_down_sync(0xFFFFFFFFu, acc, off);
        if (lane == 0) s_r[wrp] = acc;
        __syncthreads();
        if (tid < 32) {
            float t = (lane < NW) ? s_r[lane] : 0.0f;
#pragma unroll
            for (int off = 8; off > 0; off >>= 1)
                t += __shfl_down_sync(0xFFFFFFFFu, t, off);
            if (lane == 0) gen[b] = t;
        }
        __syncthreads();
    }

    // C2: stealing pool, rows 4095 down to POOL0 (latest-written = L2-warm first)
    for (;;) {
        if (tid == 0) s_row = (int)atomicAdd(&g_rowcnt, 1u);
        __syncthreads();
        const int r = s_row;
        const int b = BB - 1 - r;
        if (b < POOL0) break;

        const long base = (long)b * TT + coff;
        const float4* cp = reinterpret_cast<const float4*>(cum       + base);
        const float4* bp = reinterpret_cast<const float4*>(baselines + base);
        const float4* lp = reinterpret_cast<const float4*>(log_probs + base);

        float4 c0v = cp[0],      c1v = cp[1];
        float4 b0v = bp[0],      b1v = bp[1];
        float4 l0v = __ldcs(lp), l1v = __ldcs(lp + 1);

        float acc = 0.0f, a;
        a = fminf(fmaxf(c0v.x - b0v.x - m0.x, -CLIPV), CLIPV); acc = fmaf(a, l0v.x, acc);
        a = fminf(fmaxf(c0v.y - b0v.y - m0.y, -CLIPV), CLIPV); acc = fmaf(a, l0v.y, acc);
        a = fminf(fmaxf(c0v.z - b0v.z - m0.z, -CLIPV), CLIPV); acc = fmaf(a, l0v.z, acc);
        a = fminf(fmaxf(c0v.w - b0v.w - m0.w, -CLIPV), CLIPV); acc = fmaf(a, l0v.w, acc);
        a = fminf(fmaxf(c1v.x - b1v.x - m1.x, -CLIPV), CLIPV); acc = fmaf(a, l1v.x, acc);
        a = fminf(fmaxf(c1v.y - b1v.y - m1.y, -CLIPV), CLIPV); acc = fmaf(a, l1v.y, acc);
        a = fminf(fmaxf(c1v.z - b1v.z - m1.z, -CLIPV), CLIPV); acc = fmaf(a, l1v.z, acc);
        a = fminf(fmaxf(c1v.w - b1v.w - m1.w, -CLIPV), CLIPV); acc = fmaf(a, l1v.w, acc);

#pragma unroll
        for (int off = 16; off > 0; off >>= 1)
            acc += __shfl_down_sync(0xFFFFFFFFu, acc, off);
        if (lane == 0) s_r[wrp] = acc;
        __syncthreads();
        if (tid < 32) {
            float t = (lane < NW) ? s_r[lane] : 0.0f;
#pragma unroll
            for (int off = 8; off > 0; off >>= 1)
                t += __shfl_down_sync(0xFFFFFFFFu, t, off);
            if (lane == 0) gen[b] = t;
        }
        __syncthreads();
    }
}

// -----------------------------------------------------------------------------
extern "C" void kernel_launch(void* const* d_in, const int* in_sizes, int n_in,
                              void* d_out, int out_size) {
    const float* log_probs = (const float*)d_in[0];
    const float* logits    = (const float*)d_in[1];
    const float* weight    = (const float*)d_in[2];
    const float* baselines = (const float*)d_in[3];

    const int smem_bytes = CROWS * TT * sizeof(float);   // 64 KB dynamic
    cudaFuncSetAttribute(fused_all, cudaFuncAttributeMaxDynamicSharedMemorySize, smem_bytes);
    fused_all<<<NBLK, THREADS, smem_bytes>>>(log_probs, logits, weight, baselines,
                                             (float*)d_out);
}

// round 10
// speedup vs baseline: 1.2241x; 1.2241x over previous
#include <cuda_runtime.h>

#define BB 4096
#define TT 4096
#define GAMMA  0.99f
#define CLIPV  5.0f

#define THREADS 512
#define LPT 8                  // columns per thread (512*8 = 4096)
#define NW (THREADS / 32)      // 16 warps
#define NBLK 444               // 3 blocks/SM * 148 SMs — all co-resident

#define GAMMA8   0.92274469f   // 0.99^8
#define GAMMA256 0.07631496f   // 0.99^256
#define LOG2G   (-0.014499569695115089f)   // log2(0.99)

__device__ float g_partial[NBLK * TT];
__device__ float g_colmean[TT];
__device__ unsigned g_cnt[2];
__device__ volatile unsigned g_epoch;
__device__ unsigned g_rowcnt;

__device__ __forceinline__ void grid_barrier(unsigned* cnt, unsigned target) {
    __syncthreads();
    if (threadIdx.x == 0) {
        __threadfence();
        if (atomicAdd(cnt, 1u) == NBLK - 1u) {
            *cnt = 0;
            __threadfence();
            g_epoch = target;
        } else {
            while (g_epoch != target) __nanosleep(64);
            __threadfence();
        }
    }
    __syncthreads();
}

// -----------------------------------------------------------------------------
__global__ __launch_bounds__(THREADS, 3)
void fused_all(const float* __restrict__ log_probs,
               const float* __restrict__ logits,
               const float* __restrict__ weight,
               const float* __restrict__ baselines,
               float* __restrict__ out) {
    __shared__ float s_w[2][NW];
    __shared__ float s_s[2][NW];
    __shared__ float s_pb[NW * 32];
    __shared__ float s_r[NW];
    __shared__ unsigned s_base;
    __shared__ int s_row;

    const int tid  = threadIdx.x;
    const int lane = tid & 31;
    const int wrp  = tid >> 5;
    const int bid  = blockIdx.x;

    if (tid == 0) s_base = g_epoch;
    __syncthreads();
    const unsigned base_e = s_base;

    float* gen = out;
    float* cum = out + BB;

    const float pw = exp2f((float)(31 - lane) * 8.0f * LOG2G);
    const long coff = (long)tid * LPT;

    float pacc[LPT];
#pragma unroll
    for (int k = 0; k < LPT; k++) pacc[k] = 0.0f;

    // ============================ PHASE A ====================================
    int buf = 0;
    for (int b = bid; b < BB; b += NBLK) {
        const long base = (long)b * TT + coff;
        const float4* lgp = reinterpret_cast<const float4*>(logits + base);
        const float4* wtp = reinterpret_cast<const float4*>(weight + base);
        const float4* bp  = reinterpret_cast<const float4*>(baselines + base);

        float c[LPT];
#pragma unroll
        for (int i = 0; i < LPT / 4; i++) {
            float4 lg = __ldcs(lgp + i);
            float4 wt = __ldcs(wtp + i);
            float xs[4] = {lg.x, lg.y, lg.z, lg.w};
            float ws[4] = {wt.x, wt.y, wt.z, wt.w};
#pragma unroll
            for (int k = 0; k < 4; k++) {
                float x  = xs[k];
                float ls = fminf(x, 0.0f) - __logf(1.0f + __expf(-fabsf(x)));
                c[i * 4 + k] = ws[k] * ls;
            }
        }

        // hoisted baselines load: DRAM latency overlaps the scan chain below
        float4 ba0 = bp[0];
        float4 ba1 = bp[1];

        // thread-local reverse scan
        float carry = 0.0f;
#pragma unroll
        for (int i = LPT - 1; i >= 0; i--) {
            carry = c[i] + GAMMA * carry;
            c[i] = carry;
        }

        // warp reverse inclusive scan, ratio gamma^8
        float v = carry;
        float f = GAMMA8;
#pragma unroll
        for (int step = 1; step < 32; step <<= 1) {
            float up = __shfl_down_sync(0xFFFFFFFFu, v, step);
            if (lane + step < 32) v += f * up;
            f *= f;
        }
        if (lane == 0) s_w[buf][wrp] = v;
        __syncthreads();

        if (wrp == 0 && lane < NW) {
            float x = s_w[buf][lane];
            float g = GAMMA256;
#pragma unroll
            for (int step = 1; step < NW; step <<= 1) {
                float up = __shfl_down_sync(0xFFFFu, x, step, NW);
                if (lane + step < NW) x += g * up;
                g *= g;
            }
            s_s[buf][lane] = x;
        }
        __syncthreads();

        float ve = __shfl_down_sync(0xFFFFFFFFu, v, 1);
        if (lane == 31) ve = 0.0f;
        float Xw = (wrp + 1 < NW) ? s_s[buf][wrp + 1] : 0.0f;
        float T  = ve + pw * Xw;

        float p = GAMMA;
#pragma unroll
        for (int k = LPT - 1; k >= 0; k--) {
            c[k] = fmaf(p, T, c[k]);
            p *= GAMMA;
        }

        float4* cp = reinterpret_cast<float4*>(cum + base);
        cp[0] = make_float4(c[0], c[1], c[2], c[3]);
        cp[1] = make_float4(c[4], c[5], c[6], c[7]);

        pacc[0] += c[0] - ba0.x;
        pacc[1] += c[1] - ba0.y;
        pacc[2] += c[2] - ba0.z;
        pacc[3] += c[3] - ba0.w;
        pacc[4] += c[4] - ba1.x;
        pacc[5] += c[5] - ba1.y;
        pacc[6] += c[6] - ba1.z;
        pacc[7] += c[7] - ba1.w;
        buf ^= 1;
    }

    {
        float4* pp = reinterpret_cast<float4*>(g_partial + (long)bid * TT + coff);
#pragma unroll
        for (int i = 0; i < LPT / 4; i++)
            pp[i] = make_float4(pacc[i*4+0], pacc[i*4+1], pacc[i*4+2], pacc[i*4+3]);
    }

    grid_barrier(&g_cnt[0], base_e + 1);

    // ============================ PHASE B ====================================
    if (bid < 128) {
        const int c0 = bid * 32;
        float a = 0.0f;
#pragma unroll 4
        for (int r = wrp; r < NBLK; r += NW)
            a += g_partial[(long)r * TT + c0 + lane];
        s_pb[wrp * 32 + lane] = a;
        __syncthreads();
        if (wrp == 0) {
            float m = 0.0f;
#pragma unroll
            for (int k = 0; k < NW; k++) m += s_pb[k * 32 + lane];
            g_colmean[c0 + lane] = m * (1.0f / BB);
        }
    } else if (bid == 128 && tid == 0) {
        g_rowcnt = 0;
    }

    grid_barrier(&g_cnt[1], base_e + 2);

    // ============================ PHASE C ====================================
    // descending dynamic work-stealing: newest-written rows first (L2-warm).
    const float4* mp = reinterpret_cast<const float4*>(g_colmean + coff);
    const float4 m0 = mp[0], m1 = mp[1];

    for (;;) {
        if (tid == 0) s_row = (int)atomicAdd(&g_rowcnt, 1u);
        __syncthreads();
        const int r = s_row;
        if (r >= BB) break;
        const int b = BB - 1 - r;

        const long base = (long)b * TT + coff;
        const float4* cp = reinterpret_cast<const float4*>(cum       + base);
        const float4* bp = reinterpret_cast<const float4*>(baselines + base);
        const float4* lp = reinterpret_cast<const float4*>(log_probs + base);

        // all three streams dead after this read: evict-first everywhere
        float4 c0v = __ldcs(cp),     c1v = __ldcs(cp + 1);
        float4 b0v = __ldcs(bp),     b1v = __ldcs(bp + 1);
        float4 l0v = __ldcs(lp),     l1v = __ldcs(lp + 1);

        float acc = 0.0f, a;
        a = fminf(fmaxf(c0v.x - b0v.x - m0.x, -CLIPV), CLIPV); acc = fmaf(a, l0v.x, acc);
        a = fminf(fmaxf(c0v.y - b0v.y - m0.y, -CLIPV), CLIPV); acc = fmaf(a, l0v.y, acc);
        a = fminf(fmaxf(c0v.z - b0v.z - m0.z, -CLIPV), CLIPV); acc = fmaf(a, l0v.z, acc);
        a = fminf(fmaxf(c0v.w - b0v.w - m0.w, -CLIPV), CLIPV); acc = fmaf(a, l0v.w, acc);
        a = fminf(fmaxf(c1v.x - b1v.x - m1.x, -CLIPV), CLIPV); acc = fmaf(a, l1v.x, acc);
        a = fminf(fmaxf(c1v.y - b1v.y - m1.y, -CLIPV), CLIPV); acc = fmaf(a, l1v.y, acc);
        a = fminf(fmaxf(c1v.z - b1v.z - m1.z, -CLIPV), CLIPV); acc = fmaf(a, l1v.z, acc);
        a = fminf(fmaxf(c1v.w - b1v.w - m1.w, -CLIPV), CLIPV); acc = fmaf(a, l1v.w, acc);

#pragma unroll
        for (int off = 16; off > 0; off >>= 1)
            acc += __shfl_down_sync(0xFFFFFFFFu, acc, off);
        if (lane == 0) s_r[wrp] = acc;
        __syncthreads();
        if (tid < 32) {
            float t = (lane < NW) ? s_r[lane] : 0.0f;
#pragma unroll
            for (int off = 8; off > 0; off >>= 1)
                t += __shfl_down_sync(0xFFFFFFFFu, t, off);
            if (lane == 0) gen[b] = t;
        }
        __syncthreads();
    }
}

// -----------------------------------------------------------------------------
extern "C" void kernel_launch(void* const* d_in, const int* in_sizes, int n_in,
                              void* d_out, int out_size) {
    const float* log_probs = (const float*)d_in[0];
    const float* logits    = (const float*)d_in[1];
    const float* weight    = (const float*)d_in[2];
    const float* baselines = (const float*)d_in[3];

    fused_all<<<NBLK, THREADS>>>(log_probs, logits, weight, baselines, (float*)d_out);
}